// round 2
// baseline (speedup 1.0000x reference)
#include <cuda_runtime.h>
#include <cuda_bf16.h>
#include <math.h>

// ---------------------------------------------------------------------------
// SparseMOE: B=8, S=4096, D_IN=1024, D_OUT=1024, E=8, TOP_K=2
// out  = sum over token's top-2 experts of w_e * (x @ W_e^T + b_e)
// also outputs router_logits [T, E]  (gate MLP is LINEAR -> fold into one mat)
// ---------------------------------------------------------------------------

#define T_TOK   32768
#define D_IN    1024
#define D_H     512
#define D_OUT   1024
#define NEXP    8
#define OUT_MAIN (T_TOK * D_OUT)          // 33,554,432 floats
#define MT      128                        // GEMM M tile
#define NT      128                        // GEMM N tile
#define KT      8                          // GEMM K step
#define PERM_MAX (2 * T_TOK + NEXP * MT)   // 66,560

// ---- device scratch (allocation-free rule: __device__ globals) ------------
__device__ float g_Wc[NEXP * D_IN];   // fused gate weight  [E][D_IN]
__device__ float g_bc[NEXP];          // fused gate bias
__device__ int   g_cnt[NEXP];
__device__ int   g_fill[NEXP];
__device__ int   g_off[NEXP + 1];
__device__ int   g_exp[2 * T_TOK];    // per-token chosen experts
__device__ float g_wt[2 * T_TOK];     // per-token renormalized weights
__device__ int   g_perm[PERM_MAX];    // grouped (by expert) token indices
__device__ float g_pw[PERM_MAX];      // matching combine weight

// ---------------------------------------------------------------------------
// K0: init output main region to 0, perm to -1, counters to 0 (grid-stride)
// ---------------------------------------------------------------------------
__global__ void k_init(float* __restrict__ out) {
    int stride = gridDim.x * blockDim.x;
    int n4 = OUT_MAIN / 4;
    for (int i = blockIdx.x * blockDim.x + threadIdx.x; i < n4; i += stride)
        reinterpret_cast<float4*>(out)[i] = make_float4(0.f, 0.f, 0.f, 0.f);
    int i = blockIdx.x * blockDim.x + threadIdx.x;
    if (i < PERM_MAX) g_perm[i] = -1;
    if (i < NEXP) { g_cnt[i] = 0; g_fill[i] = 0; }
}

// ---------------------------------------------------------------------------
// K1: fused gate weight  Wc[e][k] = sum_j W2[e][j] * W1[j][k]  (fp64 accum)
//     bc[e] = b2[e] + sum_j W2[e][j] * b1[j]
// ---------------------------------------------------------------------------
__global__ void k_wc(const float* __restrict__ w1, const float* __restrict__ b1,
                     const float* __restrict__ w2, const float* __restrict__ b2) {
    int idx = blockIdx.x * blockDim.x + threadIdx.x;
    if (idx < NEXP * D_IN) {
        int e = idx >> 10;
        int k = idx & (D_IN - 1);
        const float* w2r = w2 + e * D_H;
        double s = 0.0;
        for (int j = 0; j < D_H; j++)
            s += (double)w2r[j] * (double)w1[j * D_IN + k];
        g_Wc[idx] = (float)s;
    }
    if (blockIdx.x == 0 && threadIdx.x < NEXP) {
        int e = threadIdx.x;
        double s = (double)b2[e];
        for (int j = 0; j < D_H; j++)
            s += (double)w2[e * D_H + j] * (double)b1[j];
        g_bc[e] = (float)s;
    }
}

// ---------------------------------------------------------------------------
// K2: router — one warp per token. logits = x @ Wc^T + bc, top-2, renorm.
// ---------------------------------------------------------------------------
__global__ __launch_bounds__(256) void k_router(const float* __restrict__ x,
                                                float* __restrict__ logits_out) {
    __shared__ float sWc[NEXP][D_IN];
    __shared__ float sbc[NEXP];
    int tid = threadIdx.x;
    for (int i = tid; i < NEXP * D_IN; i += 256)
        (&sWc[0][0])[i] = g_Wc[i];
    if (tid < NEXP) sbc[tid] = g_bc[tid];
    __syncthreads();

    int warp = tid >> 5, lane = tid & 31;
    int t = blockIdx.x * 8 + warp;   // T_TOK is a multiple of 8

    float acc[NEXP];
#pragma unroll
    for (int e = 0; e < NEXP; e++) acc[e] = 0.f;

    const float* xr = x + (size_t)t * D_IN;
    for (int k = lane; k < D_IN; k += 32) {
        float xv = xr[k];
#pragma unroll
        for (int e = 0; e < NEXP; e++) acc[e] += xv * sWc[e][k];
    }
#pragma unroll
    for (int e = 0; e < NEXP; e++) {
#pragma unroll
        for (int o = 16; o > 0; o >>= 1)
            acc[e] += __shfl_xor_sync(0xffffffffu, acc[e], o);
    }

    if (lane == 0) {
        float l[NEXP];
#pragma unroll
        for (int e = 0; e < NEXP; e++) l[e] = acc[e] + sbc[e];

        // top-2 with jax.lax.top_k tie-break (lower index wins on ties)
        int a = 0;
#pragma unroll
        for (int e = 1; e < NEXP; e++) if (l[e] > l[a]) a = e;
        int b = (a == 0) ? 1 : 0;
#pragma unroll
        for (int e = 0; e < NEXP; e++)
            if (e != a && e != b && l[e] > l[b]) b = e;

        // renormalized top-2 softmax weights: wa = exp(la)/(exp(la)+exp(lb))
        float eb_ = expf(l[b] - l[a]);          // <= 1, stable
        float inv = 1.f / (1.f + eb_);
        float wa = inv;
        float wb = eb_ * inv;

        g_exp[2 * t]     = a;  g_wt[2 * t]     = wa;
        g_exp[2 * t + 1] = b;  g_wt[2 * t + 1] = wb;
        atomicAdd(&g_cnt[a], 1);
        atomicAdd(&g_cnt[b], 1);

        if (logits_out) {
            float* lo = logits_out + (size_t)t * NEXP;
#pragma unroll
            for (int e = 0; e < NEXP; e++) lo[e] = l[e];
        }
    }
}

// ---------------------------------------------------------------------------
// K3: tiny exclusive scan with per-expert padding to MT
// ---------------------------------------------------------------------------
__global__ void k_scan() {
    if (threadIdx.x == 0 && blockIdx.x == 0) {
        int o = 0;
        for (int e = 0; e < NEXP; e++) {
            g_off[e] = o;
            o += ((g_cnt[e] + MT - 1) / MT) * MT;
        }
        g_off[NEXP] = o;
    }
}

// ---------------------------------------------------------------------------
// K4: scatter tokens into per-expert grouped lists
// ---------------------------------------------------------------------------
__global__ void k_scatter() {
    int t = blockIdx.x * blockDim.x + threadIdx.x;
    if (t < T_TOK) {
#pragma unroll
        for (int j = 0; j < 2; j++) {
            int e = g_exp[2 * t + j];
            int pos = g_off[e] + atomicAdd(&g_fill[e], 1);
            g_perm[pos] = t;
            g_pw[pos]   = g_wt[2 * t + j];
        }
    }
}

// ---------------------------------------------------------------------------
// K5: per-expert GEMM.  C[128 rows, 128 cols] per block, fp32 SIMT 8x8 micro.
//     A rows gathered via g_perm; epilogue: atomicAdd(w * (acc + bias)).
// ---------------------------------------------------------------------------
__global__ __launch_bounds__(256, 2) void k_expert(
    const float* __restrict__ x, const float* __restrict__ ew,
    const float* __restrict__ eb, float* __restrict__ out) {

    __shared__ float As[KT][MT + 4];
    __shared__ float Bs[KT][NT + 4];
    __shared__ int   sRow[MT];
    __shared__ float sWt[MT];
    __shared__ int   sE;

    int mbase = blockIdx.y * MT;
    int nbase = blockIdx.x * NT;
    if (mbase >= g_off[NEXP]) return;   // uniform over block

    int tid = threadIdx.x;
    if (tid == 0) {
        int e = 0;
        while (e + 1 < NEXP && g_off[e + 1] <= mbase) e++;
        sE = e;
    }
    if (tid < MT) {
        int p = mbase + tid;
        int r = g_perm[p];
        sRow[tid] = r;
        sWt[tid]  = (r >= 0) ? g_pw[p] : 0.f;
    }
    __syncthreads();

    int e = sE;
    const float* W = ew + (size_t)e * D_OUT * D_IN;

    // loading lanes: each thread loads one float4 of A and one of B per k-step
    int lr = tid >> 1;          // 0..127
    int lc = (tid & 1) * 4;     // 0 or 4
    int grow = sRow[lr]; if (grow < 0) grow = 0;
    const float* aptr = x + (size_t)grow * D_IN + lc;
    const float* bptr = W + (size_t)(nbase + lr) * D_IN + lc;

    int tx = tid & 15;          // col group
    int ty = tid >> 4;          // row group

    float acc[8][8];
#pragma unroll
    for (int i = 0; i < 8; i++)
#pragma unroll
        for (int j = 0; j < 8; j++) acc[i][j] = 0.f;

    for (int k0 = 0; k0 < D_IN; k0 += KT) {
        float4 av = *reinterpret_cast<const float4*>(aptr + k0);
        float4 bv = *reinterpret_cast<const float4*>(bptr + k0);
        __syncthreads();
        As[lc + 0][lr] = av.x; As[lc + 1][lr] = av.y;
        As[lc + 2][lr] = av.z; As[lc + 3][lr] = av.w;
        Bs[lc + 0][lr] = bv.x; Bs[lc + 1][lr] = bv.y;
        Bs[lc + 2][lr] = bv.z; Bs[lc + 3][lr] = bv.w;
        __syncthreads();
#pragma unroll
        for (int kk = 0; kk < KT; kk++) {
            float4 a0 = *reinterpret_cast<const float4*>(&As[kk][ty * 4]);
            float4 a1 = *reinterpret_cast<const float4*>(&As[kk][64 + ty * 4]);
            float4 b0 = *reinterpret_cast<const float4*>(&Bs[kk][tx * 4]);
            float4 b1 = *reinterpret_cast<const float4*>(&Bs[kk][64 + tx * 4]);
            float a[8] = {a0.x, a0.y, a0.z, a0.w, a1.x, a1.y, a1.z, a1.w};
            float b[8] = {b0.x, b0.y, b0.z, b0.w, b1.x, b1.y, b1.z, b1.w};
#pragma unroll
            for (int i = 0; i < 8; i++)
#pragma unroll
                for (int j = 0; j < 8; j++) acc[i][j] += a[i] * b[j];
        }
    }

    // bias for this thread's 8 output cols
    float4 ebv0 = *reinterpret_cast<const float4*>(eb + (size_t)e * D_OUT + nbase + tx * 4);
    float4 ebv1 = *reinterpret_cast<const float4*>(eb + (size_t)e * D_OUT + nbase + 64 + tx * 4);
    float bias[8] = {ebv0.x, ebv0.y, ebv0.z, ebv0.w, ebv1.x, ebv1.y, ebv1.z, ebv1.w};

#pragma unroll
    for (int rm = 0; rm < 2; rm++) {
#pragma unroll
        for (int i = 0; i < 4; i++) {
            int ri = rm * 64 + ty * 4 + i;
            int token = sRow[ri];
            if (token < 0) continue;
            float wt = sWt[ri];
            float* orow = out + (size_t)token * D_OUT + nbase;
#pragma unroll
            for (int cn = 0; cn < 2; cn++) {
#pragma unroll
                for (int j = 0; j < 4; j++) {
                    int n = cn * 64 + tx * 4 + j;
                    float v = wt * (acc[rm * 4 + i][cn * 4 + j] + bias[cn * 4 + j]);
                    atomicAdd(orow + n, v);
                }
            }
        }
    }
}

// ---------------------------------------------------------------------------
// launcher
// ---------------------------------------------------------------------------
extern "C" void kernel_launch(void* const* d_in, const int* in_sizes, int n_in,
                              void* d_out, int out_size) {
    const float *x = nullptr, *w1 = nullptr, *b1 = nullptr, *w2 = nullptr,
                *b2 = nullptr, *ew = nullptr, *ebp = nullptr;
    // identify inputs robustly by element count (all distinct)
    for (int i = 0; i < n_in; i++) {
        switch (in_sizes[i]) {
            case 33554432: x   = (const float*)d_in[i]; break; // [8,4096,1024]
            case 524288:   w1  = (const float*)d_in[i]; break; // [512,1024]
            case 512:      b1  = (const float*)d_in[i]; break; // [512]
            case 4096:     w2  = (const float*)d_in[i]; break; // [8,512]
            case 8:        b2  = (const float*)d_in[i]; break; // [8]
            case 8388608:  ew  = (const float*)d_in[i]; break; // [8,1024,1024]
            case 8192:     ebp = (const float*)d_in[i]; break; // [8,1024]
            default: break;
        }
    }
    float* out = (float*)d_out;
    float* logits = (out_size >= OUT_MAIN + T_TOK * NEXP) ? out + OUT_MAIN : nullptr;

    k_init<<<1024, 256>>>(out);
    k_wc<<<(NEXP * D_IN + 255) / 256, 256>>>(w1, b1, w2, b2);
    k_router<<<T_TOK / 8, 256>>>(x, logits);
    k_scan<<<1, 32>>>();
    k_scatter<<<(T_TOK + 255) / 256, 256>>>();
    dim3 g(D_OUT / NT, 2 * T_TOK / MT + NEXP);
    k_expert<<<g, 256>>>(x, ew, ebp, out);
}

// round 8
// speedup vs baseline: 2.2390x; 2.2390x over previous
#include <cuda_runtime.h>
#include <cuda_bf16.h>
#include <math.h>
#include <stdint.h>

// ---------------------------------------------------------------------------
// SparseMOE: B=8, S=4096, D_IN=1024, D_OUT=1024, E=8, TOP_K=2
//   out = sum over token's top-2 experts of w_e * (x @ W_e^T + b_e)
//   router_logits [T, E] appended after main out (gate MLP is linear -> fold)
// Expert GEMM: mma.sync bf16 3-pass split precision (hh + hl + lh), fp32 acc.
// (tcgen05 unavailable: harness compiles .target sm_100 base, not sm_100a)
// ---------------------------------------------------------------------------

#define T_TOK   32768
#define D_IN    1024
#define D_H     512
#define D_OUT   1024
#define NEXP    8
#define OUT_MAIN (T_TOK * D_OUT)
#define MT      128                        // GEMM M tile
#define NT      128                        // GEMM N tile
#define BK      32                         // K chunk
#define NCHUNK  (D_IN / BK)                // 32
#define PERM_MAX (2 * T_TOK + NEXP * MT)   // 66560
#define MTILES  (PERM_MAX / MT)            // 520

// SMEM stage layout: 4 buffers [128 rows][BK bf16], row stride 80B (pad 16B)
#define ROWB       80
#define BUF_SZ     (128 * ROWB)            // 10240
#define OFF_AHI    0
#define OFF_ALO    BUF_SZ
#define OFF_BHI    (2 * BUF_SZ)
#define OFF_BLO    (3 * BUF_SZ)
#define STAGE_SZ   (4 * BUF_SZ)            // 40960
#define SMEM_DYN   (2 * STAGE_SZ)          // 81920

// ---- device scratch -------------------------------------------------------
__device__ float g_Wc[NEXP * D_IN];
__device__ float g_bc[NEXP];
__device__ int   g_cnt[NEXP];
__device__ int   g_fill[NEXP];
__device__ int   g_off[NEXP + 1];
__device__ int   g_exp[2 * T_TOK];
__device__ float g_wt[2 * T_TOK];
__device__ int   g_pos[2 * T_TOK];          // token -> its 2 slots in perm
__device__ int   g_perm[PERM_MAX];          // grouped token indices (-1 = pad)
__device__ float g_part[PERM_MAX * D_OUT];  // per-slot raw expert outputs
__device__ __nv_bfloat16 g_xhi[T_TOK * D_IN];
__device__ __nv_bfloat16 g_xlo[T_TOK * D_IN];
__device__ __nv_bfloat16 g_whi[NEXP * D_OUT * D_IN];
__device__ __nv_bfloat16 g_wlo[NEXP * D_OUT * D_IN];

// ---------------------------------------------------------------------------
// PTX helpers (all portable to .target sm_100 base: sm_80-era ISA)
// ---------------------------------------------------------------------------
__device__ __forceinline__ uint32_t smem_u32(const void* p) {
    uint32_t a;
    asm("{ .reg .u64 t; cvta.to.shared.u64 t, %1; cvt.u32.u64 %0, t; }"
        : "=r"(a) : "l"(p));
    return a;
}
#define CP16(dst, src) \
    asm volatile("cp.async.cg.shared.global [%0], [%1], 16;" \
                 :: "r"(dst), "l"(src) : "memory")
#define CP_COMMIT() asm volatile("cp.async.commit_group;" ::: "memory")
#define CP_WAIT1()  asm volatile("cp.async.wait_group 1;" ::: "memory")
#define CP_WAIT0()  asm volatile("cp.async.wait_group 0;" ::: "memory")

__device__ __forceinline__ void ldsm4(uint32_t* r, uint32_t addr) {
    asm volatile("ldmatrix.sync.aligned.m8n8.x4.shared.b16 {%0,%1,%2,%3}, [%4];"
                 : "=r"(r[0]), "=r"(r[1]), "=r"(r[2]), "=r"(r[3]) : "r"(addr));
}
__device__ __forceinline__ void mma_bf16(float* c, const uint32_t* a, const uint32_t* b) {
    asm volatile("mma.sync.aligned.m16n8k16.row.col.f32.bf16.bf16.f32 "
                 "{%0,%1,%2,%3}, {%4,%5,%6,%7}, {%8,%9}, {%0,%1,%2,%3};"
                 : "+f"(c[0]), "+f"(c[1]), "+f"(c[2]), "+f"(c[3])
                 : "r"(a[0]), "r"(a[1]), "r"(a[2]), "r"(a[3]),
                   "r"(b[0]), "r"(b[1]));
}

// ---------------------------------------------------------------------------
// K0: init perm/counters
// ---------------------------------------------------------------------------
__global__ void k_init() {
    int i = blockIdx.x * blockDim.x + threadIdx.x;
    if (i < PERM_MAX) g_perm[i] = -1;
    if (i < NEXP) { g_cnt[i] = 0; g_fill[i] = 0; }
}

// ---------------------------------------------------------------------------
// K1: fused gate weight (fp64 accum — router decisions must be exact)
// ---------------------------------------------------------------------------
__global__ void k_wc(const float* __restrict__ w1, const float* __restrict__ b1,
                     const float* __restrict__ w2, const float* __restrict__ b2) {
    int idx = blockIdx.x * blockDim.x + threadIdx.x;
    if (idx < NEXP * D_IN) {
        int e = idx >> 10, k = idx & (D_IN - 1);
        const float* w2r = w2 + e * D_H;
        double s = 0.0;
        for (int j = 0; j < D_H; j++) s += (double)w2r[j] * (double)w1[j * D_IN + k];
        g_Wc[idx] = (float)s;
    }
    if (blockIdx.x == 0 && threadIdx.x < NEXP) {
        int e = threadIdx.x;
        double s = (double)b2[e];
        for (int j = 0; j < D_H; j++) s += (double)w2[e * D_H + j] * (double)b1[j];
        g_bc[e] = (float)s;
    }
}

// ---------------------------------------------------------------------------
// K1b: split fp32 -> bf16 hi + bf16 lo for x and expert weights
// ---------------------------------------------------------------------------
__device__ __forceinline__ void split4(float4 v, __nv_bfloat162* hi2, __nv_bfloat162* lo2) {
    __nv_bfloat16 h0 = __float2bfloat16_rn(v.x);
    __nv_bfloat16 h1 = __float2bfloat16_rn(v.y);
    __nv_bfloat16 h2 = __float2bfloat16_rn(v.z);
    __nv_bfloat16 h3 = __float2bfloat16_rn(v.w);
    hi2[0] = __nv_bfloat162(h0, h1);
    hi2[1] = __nv_bfloat162(h2, h3);
    lo2[0] = __nv_bfloat162(__float2bfloat16_rn(v.x - __bfloat162float(h0)),
                            __float2bfloat16_rn(v.y - __bfloat162float(h1)));
    lo2[1] = __nv_bfloat162(__float2bfloat16_rn(v.z - __bfloat162float(h2)),
                            __float2bfloat16_rn(v.w - __bfloat162float(h3)));
}
__global__ void k_split(const float4* __restrict__ x4, const float4* __restrict__ w4) {
    int stride = gridDim.x * blockDim.x;
    int nx4 = T_TOK * D_IN / 4, nw4 = NEXP * D_OUT * D_IN / 4;
    __nv_bfloat162* xh = reinterpret_cast<__nv_bfloat162*>(g_xhi);
    __nv_bfloat162* xl = reinterpret_cast<__nv_bfloat162*>(g_xlo);
    __nv_bfloat162* wh = reinterpret_cast<__nv_bfloat162*>(g_whi);
    __nv_bfloat162* wl = reinterpret_cast<__nv_bfloat162*>(g_wlo);
    for (int i = blockIdx.x * blockDim.x + threadIdx.x; i < nx4; i += stride) {
        __nv_bfloat162 h2[2], l2[2];
        split4(x4[i], h2, l2);
        xh[2 * i] = h2[0]; xh[2 * i + 1] = h2[1];
        xl[2 * i] = l2[0]; xl[2 * i + 1] = l2[1];
    }
    for (int i = blockIdx.x * blockDim.x + threadIdx.x; i < nw4; i += stride) {
        __nv_bfloat162 h2[2], l2[2];
        split4(w4[i], h2, l2);
        wh[2 * i] = h2[0]; wh[2 * i + 1] = h2[1];
        wl[2 * i] = l2[0]; wl[2 * i + 1] = l2[1];
    }
}

// ---------------------------------------------------------------------------
// K2: router — one warp per token
// ---------------------------------------------------------------------------
__global__ __launch_bounds__(256) void k_router(const float* __restrict__ x,
                                                float* __restrict__ logits_out) {
    __shared__ float sWc[NEXP][D_IN];
    __shared__ float sbc[NEXP];
    int tid = threadIdx.x;
    for (int i = tid; i < NEXP * D_IN; i += 256) (&sWc[0][0])[i] = g_Wc[i];
    if (tid < NEXP) sbc[tid] = g_bc[tid];
    __syncthreads();

    int warp = tid >> 5, lane = tid & 31;
    int t = blockIdx.x * 8 + warp;

    float acc[NEXP];
#pragma unroll
    for (int e = 0; e < NEXP; e++) acc[e] = 0.f;
    const float* xr = x + (size_t)t * D_IN;
    for (int k = lane; k < D_IN; k += 32) {
        float xv = xr[k];
#pragma unroll
        for (int e = 0; e < NEXP; e++) acc[e] += xv * sWc[e][k];
    }
#pragma unroll
    for (int e = 0; e < NEXP; e++)
#pragma unroll
        for (int o = 16; o > 0; o >>= 1)
            acc[e] += __shfl_xor_sync(0xffffffffu, acc[e], o);

    if (lane == 0) {
        float l[NEXP];
#pragma unroll
        for (int e = 0; e < NEXP; e++) l[e] = acc[e] + sbc[e];
        int a = 0;
#pragma unroll
        for (int e = 1; e < NEXP; e++) if (l[e] > l[a]) a = e;
        int b = (a == 0) ? 1 : 0;
#pragma unroll
        for (int e = 0; e < NEXP; e++)
            if (e != a && e != b && l[e] > l[b]) b = e;
        float eb_ = expf(l[b] - l[a]);
        float inv = 1.f / (1.f + eb_);
        g_exp[2 * t] = a;     g_wt[2 * t] = inv;
        g_exp[2 * t + 1] = b; g_wt[2 * t + 1] = eb_ * inv;
        atomicAdd(&g_cnt[a], 1);
        atomicAdd(&g_cnt[b], 1);
        if (logits_out) {
            float* lo = logits_out + (size_t)t * NEXP;
#pragma unroll
            for (int e = 0; e < NEXP; e++) lo[e] = l[e];
        }
    }
}

// ---------------------------------------------------------------------------
// K3/K4: scan + scatter
// ---------------------------------------------------------------------------
__global__ void k_scan() {
    if (threadIdx.x == 0 && blockIdx.x == 0) {
        int o = 0;
        for (int e = 0; e < NEXP; e++) {
            g_off[e] = o;
            o += ((g_cnt[e] + MT - 1) / MT) * MT;
        }
        g_off[NEXP] = o;
    }
}
__global__ void k_scatter() {
    int t = blockIdx.x * blockDim.x + threadIdx.x;
    if (t < T_TOK) {
#pragma unroll
        for (int j = 0; j < 2; j++) {
            int e = g_exp[2 * t + j];
            int pos = g_off[e] + atomicAdd(&g_fill[e], 1);
            g_perm[pos] = t;
            g_pos[2 * t + j] = pos;
        }
    }
}

// ---------------------------------------------------------------------------
// K5: mma.sync expert GEMM. CTA: 128 rows x 128 cols, K=1024 in BK=32 chunks.
//     8 warps (2x4), warp tile m64 x n32, m16n8k16 bf16 -> fp32 acc.
//     3-pass split per k16: hh, hl (Blo), lh (Alo). Raw partials -> g_part.
// ---------------------------------------------------------------------------
__global__ __launch_bounds__(256, 2) void k_expert_mma() {
    extern __shared__ __align__(128) char smem[];
    __shared__ int sRow[MT];
    __shared__ int sE;

    uint32_t sb = smem_u32(smem);
    int tid = threadIdx.x;
    int wid = tid >> 5, lane = tid & 31;

    int mbase = blockIdx.y * MT;
    int nbase = blockIdx.x * NT;
    if (mbase >= g_off[NEXP]) return;   // uniform over block

    if (tid < MT) sRow[tid] = g_perm[mbase + tid];
    if (tid == 0) {
        int e = 0;
        while (e + 1 < NEXP && g_off[e + 1] <= mbase) e++;
        sE = e;
    }
    __syncthreads();
    int e = sE;

    // ---- per-thread cp.async assignments: 8 chunks of 16B per stage -------
    // id = i*256+tid -> buf(id>>9): 0 Ahi, 1 Alo, 2 Bhi, 3 Blo; r=(id&511)>>2; c=id&3
    const __nv_bfloat16* ldSrc[8];
    uint32_t ldDst[8];
#pragma unroll
    for (int i = 0; i < 8; i++) {
        int id = i * 256 + tid;
        int buf = id >> 9, rem = id & 511, r = rem >> 2, c = rem & 3;
        ldDst[i] = (uint32_t)(buf * BUF_SZ + r * ROWB + c * 16);
        if (buf < 2) {
            int tok = sRow[r]; if (tok < 0) tok = 0;
            const __nv_bfloat16* base = (buf == 0) ? g_xhi : g_xlo;
            ldSrc[i] = base + (size_t)tok * D_IN + c * 8;
        } else {
            const __nv_bfloat16* base = (buf == 2) ? g_whi : g_wlo;
            ldSrc[i] = base + ((size_t)e * D_OUT + nbase + r) * D_IN + c * 8;
        }
    }

#define ISSUE(k0, stg) do {                                                   \
    uint32_t s0 = sb + (stg) * STAGE_SZ;                                      \
    _Pragma("unroll")                                                         \
    for (int i = 0; i < 8; i++) CP16(s0 + ldDst[i], ldSrc[i] + (k0));         \
    CP_COMMIT();                                                              \
} while (0)

    // ---- fragment address offsets (within a stage) -------------------------
    int warpM = (wid >> 2) * 64;        // 0 or 64
    int warpN = (wid & 3) * 32;         // 0,32,64,96
    uint32_t aOff[4];
#pragma unroll
    for (int am = 0; am < 4; am++)
        aOff[am] = (uint32_t)((warpM + am * 16 + (lane & 15)) * ROWB
                              + (lane >> 4) * 16);
    uint32_t bOff[2];
#pragma unroll
    for (int g = 0; g < 2; g++) {
        int n = warpN + g * 16 + (lane >> 4) * 8 + (lane & 7);
        bOff[g] = (uint32_t)(n * ROWB + ((lane >> 3) & 1) * 16);
    }

    float acc[4][4][4];
#pragma unroll
    for (int i = 0; i < 4; i++)
#pragma unroll
        for (int j = 0; j < 4; j++)
#pragma unroll
            for (int q = 0; q < 4; q++) acc[i][j][q] = 0.f;

    ISSUE(0, 0);
    ISSUE(BK, 1);

    for (int ch = 0; ch < NCHUNK; ch++) {
        int stg = ch & 1;
        if (ch == NCHUNK - 1) { CP_WAIT0(); } else { CP_WAIT1(); }
        __syncthreads();

        uint32_t s0 = sb + stg * STAGE_SZ;
#pragma unroll
        for (int k16 = 0; k16 < 2; k16++) {
            uint32_t kb = (uint32_t)(k16 * 32);
            uint32_t A[4][4], Bh[2][4], Bl[2][4];
#pragma unroll
            for (int am = 0; am < 4; am++) ldsm4(A[am], s0 + OFF_AHI + aOff[am] + kb);
#pragma unroll
            for (int g = 0; g < 2; g++) {
                ldsm4(Bh[g], s0 + OFF_BHI + bOff[g] + kb);
                ldsm4(Bl[g], s0 + OFF_BLO + bOff[g] + kb);
            }
            // hh + hl
#pragma unroll
            for (int am = 0; am < 4; am++)
#pragma unroll
                for (int bn = 0; bn < 4; bn++) {
                    mma_bf16(acc[am][bn], A[am], &Bh[bn >> 1][(bn & 1) * 2]);
                    mma_bf16(acc[am][bn], A[am], &Bl[bn >> 1][(bn & 1) * 2]);
                }
            // lh (A <- Alo)
#pragma unroll
            for (int am = 0; am < 4; am++) ldsm4(A[am], s0 + OFF_ALO + aOff[am] + kb);
#pragma unroll
            for (int am = 0; am < 4; am++)
#pragma unroll
                for (int bn = 0; bn < 4; bn++)
                    mma_bf16(acc[am][bn], A[am], &Bh[bn >> 1][(bn & 1) * 2]);
        }
        __syncthreads();
        if (ch + 2 < NCHUNK) ISSUE((ch + 2) * BK, stg);
    }

    // ---- epilogue: raw partials to g_part (combine applies weights) --------
#pragma unroll
    for (int am = 0; am < 4; am++) {
        int rl = warpM + am * 16 + (lane >> 2);
        int tok0 = sRow[rl], tok1 = sRow[rl + 8];
        float* p0 = g_part + (size_t)(mbase + rl) * D_OUT + nbase;
        float* p1 = g_part + (size_t)(mbase + rl + 8) * D_OUT + nbase;
#pragma unroll
        for (int bn = 0; bn < 4; bn++) {
            int col = warpN + bn * 8 + (lane & 3) * 2;
            if (tok0 >= 0)
                *reinterpret_cast<float2*>(p0 + col) =
                    make_float2(acc[am][bn][0], acc[am][bn][1]);
            if (tok1 >= 0)
                *reinterpret_cast<float2*>(p1 + col) =
                    make_float2(acc[am][bn][2], acc[am][bn][3]);
        }
    }
}

// ---------------------------------------------------------------------------
// K6: combine — out[t] = w0*(P[p0]+b[e0]) + w1*(P[p1]+b[e1])
// ---------------------------------------------------------------------------
__global__ __launch_bounds__(256) void k_combine(const float* __restrict__ eb,
                                                 float* __restrict__ out) {
    int gid = blockIdx.x * 256 + threadIdx.x;
    int t = gid >> 8;
    int c = (gid & 255) * 4;
    int p0 = g_pos[2 * t], p1 = g_pos[2 * t + 1];
    int e0 = g_exp[2 * t], e1 = g_exp[2 * t + 1];
    float w0 = g_wt[2 * t], w1 = g_wt[2 * t + 1];
    float4 a  = *reinterpret_cast<const float4*>(g_part + (size_t)p0 * D_OUT + c);
    float4 b  = *reinterpret_cast<const float4*>(g_part + (size_t)p1 * D_OUT + c);
    float4 ba = *reinterpret_cast<const float4*>(eb + (size_t)e0 * D_OUT + c);
    float4 bb = *reinterpret_cast<const float4*>(eb + (size_t)e1 * D_OUT + c);
    float4 o;
    o.x = w0 * (a.x + ba.x) + w1 * (b.x + bb.x);
    o.y = w0 * (a.y + ba.y) + w1 * (b.y + bb.y);
    o.z = w0 * (a.z + ba.z) + w1 * (b.z + bb.z);
    o.w = w0 * (a.w + ba.w) + w1 * (b.w + bb.w);
    *reinterpret_cast<float4*>(out + (size_t)t * D_OUT + c) = o;
}

// ---------------------------------------------------------------------------
// launcher
// ---------------------------------------------------------------------------
extern "C" void kernel_launch(void* const* d_in, const int* in_sizes, int n_in,
                              void* d_out, int out_size) {
    const float *x = nullptr, *w1 = nullptr, *b1 = nullptr, *w2 = nullptr,
                *b2 = nullptr, *ew = nullptr, *ebp = nullptr;
    for (int i = 0; i < n_in; i++) {
        switch (in_sizes[i]) {
            case 33554432: x   = (const float*)d_in[i]; break;
            case 524288:   w1  = (const float*)d_in[i]; break;
            case 512:      b1  = (const float*)d_in[i]; break;
            case 4096:     w2  = (const float*)d_in[i]; break;
            case 8:        b2  = (const float*)d_in[i]; break;
            case 8388608:  ew  = (const float*)d_in[i]; break;
            case 8192:     ebp = (const float*)d_in[i]; break;
            default: break;
        }
    }
    float* out = (float*)d_out;
    float* logits = (out_size >= OUT_MAIN + T_TOK * NEXP) ? out + OUT_MAIN : nullptr;

    cudaFuncSetAttribute(k_expert_mma, cudaFuncAttributeMaxDynamicSharedMemorySize,
                         SMEM_DYN);

    k_init<<<(PERM_MAX + 255) / 256, 256>>>();
    k_wc<<<(NEXP * D_IN + 255) / 256, 256>>>(w1, b1, w2, b2);
    k_split<<<1024, 256>>>((const float4*)x, (const float4*)ew);
    k_router<<<T_TOK / 8, 256>>>(x, logits);
    k_scan<<<1, 32>>>();
    k_scatter<<<(T_TOK + 255) / 256, 256>>>();
    dim3 g(D_OUT / NT, MTILES);
    k_expert_mma<<<g, 256, SMEM_DYN>>>();
    k_combine<<<T_TOK, 256>>>(ebp, out);
}